// round 1
// baseline (speedup 1.0000x reference)
#include <cuda_runtime.h>
#include <math.h>
#include <stdint.h>

#define HASH_SIZE  (1u << 19)
#define HASH_MASK  (HASH_SIZE - 1u)
#define NTHREADS   128

struct LParams {
    float rm1[16];   // (float)(R-1)
    int   R[16];
    int   dense[16]; // 1 if R^3 <= HASH_SIZE
};

__device__ __forceinline__ float sp100(float v) {
    float z = v * 100.0f;
    if (z > 20.0f) return v;
    return 0.01f * log1pf(expf(z));
}

__device__ __forceinline__ void addin(float acc[64], float v, const float* col) {
    const float4* c4 = (const float4*)col;
#pragma unroll
    for (int q = 0; q < 16; q++) {
        float4 w = c4[q];
        acc[4*q+0] += v * w.x;
        acc[4*q+1] += v * w.y;
        acc[4*q+2] += v * w.z;
        acc[4*q+3] += v * w.w;
    }
}

__global__ void __launch_bounds__(NTHREADS) nerf_fused(
    const float* __restrict__ xin,
    const float* __restrict__ tables,
    const float* __restrict__ W0, const float* __restrict__ b0,
    const float* __restrict__ W1, const float* __restrict__ b1,
    const float* __restrict__ W2, const float* __restrict__ b2,
    float* __restrict__ out, int npts, LParams lp)
{
    extern __shared__ float sm[];
    float* sW0T = sm;                 // 71*64  (column i contiguous: W0T[i*64+j] = W0[j][i])
    float* sW1  = sW0T + 71*64;       // 64*64  row-major as given
    float* sW2T = sW1  + 64*64;       // 64*20  padded: sW2T[j*20+o] = W2[o][j]
    float* sb0  = sW2T + 64*20;       // 64
    float* sb1  = sb0 + 64;           // 64
    float* sb2  = sb1 + 64;           // 17 (pad to 32)
    float* h2s  = sb2 + 32;           // 64 * NTHREADS

    const int tid = threadIdx.x;
    for (int k = tid; k < 71*64; k += NTHREADS) { int i = k >> 6, j = k & 63; sW0T[k] = W0[j*71 + i]; }
    for (int k = tid; k < 64*64; k += NTHREADS) sW1[k] = W1[k];
    for (int k = tid; k < 64*20; k += NTHREADS) { int j = k / 20, o = k % 20; sW2T[k] = (o < 17) ? W2[o*64 + j] : 0.0f; }
    if (tid < 64) { sb0[tid] = b0[tid]; sb1[tid] = b1[tid]; }
    if (tid < 17) sb2[tid] = b2[tid];
    __syncthreads();

    int n = blockIdx.x * NTHREADS + tid;
    if (n >= npts) return;

    const float px = xin[n*3+0], py = xin[n*3+1], pz = xin[n*3+2];

    float acc[64];
#pragma unroll
    for (int j = 0; j < 64; j++) acc[j] = sb0[j];

    // ---- layer0: stream inputs 0..2 (raw x) ----
    addin(acc, px, sW0T + 0*64);
    addin(acc, py, sW0T + 1*64);
    addin(acc, pz, sW0T + 2*64);

    // ---- inputs 3..38: positional embedding, per m: sinx,siny,sinz,cosx,cosy,cosz ----
#pragma unroll 1
    for (int m = 0; m < 6; m++) {
        float f = (float)(1 << m);
        float sx, cx, sy, cy, sz, cz;
        sincosf(px * f, &sx, &cx);
        sincosf(py * f, &sy, &cy);
        sincosf(pz * f, &sz, &cz);
        const float* base = sW0T + (3 + 6*m) * 64;
        addin(acc, sx, base + 0*64);
        addin(acc, sy, base + 1*64);
        addin(acc, sz, base + 2*64);
        addin(acc, cx, base + 3*64);
        addin(acc, cy, base + 4*64);
        addin(acc, cz, base + 5*64);
    }

    // ---- inputs 39..70: hash-grid features, 2 per level ----
#pragma unroll 1
    for (int l = 0; l < 16; l++) {
        const float rm1 = lp.rm1[l];
        const int   R   = lp.R[l];
        float fx = px * rm1, fy = py * rm1, fz = pz * rm1;
        float p0x = floorf(fx), p0y = floorf(fy), p0z = floorf(fz);
        float wx = fx - p0x, wy = fy - p0y, wz = fz - p0z;
        int ix = (int)p0x, iy = (int)p0y, iz = (int)p0z;
        int x0 = max(min(ix,     R-1), 0), x1 = max(min(ix + 1, R-1), 0);
        int y0 = max(min(iy,     R-1), 0), y1 = max(min(iy + 1, R-1), 0);
        int z0 = max(min(iz,     R-1), 0), z1 = max(min(iz + 1, R-1), 0);

        uint32_t i000, i001, i010, i011, i100, i101, i110, i111;
        if (lp.dense[l]) {
            int R2 = R * R;
            int az0 = z0 * R2, az1 = z1 * R2;
            int ay0 = y0 * R,  ay1 = y1 * R;
            // corner (i,j,k): i <-> x, j <-> y, k <-> z;  idx = cx + R*cy + R^2*cz
            i000 = (uint32_t)(x0 + ay0 + az0);
            i001 = (uint32_t)(x0 + ay0 + az1);
            i010 = (uint32_t)(x0 + ay1 + az0);
            i011 = (uint32_t)(x0 + ay1 + az1);
            i100 = (uint32_t)(x1 + ay0 + az0);
            i101 = (uint32_t)(x1 + ay0 + az1);
            i110 = (uint32_t)(x1 + ay1 + az0);
            i111 = (uint32_t)(x1 + ay1 + az1);
        } else {
            uint32_t hx0 = (uint32_t)x0,               hx1 = (uint32_t)x1;
            uint32_t hy0 = (uint32_t)y0 * 2654435761u, hy1 = (uint32_t)y1 * 2654435761u;
            uint32_t hz0 = (uint32_t)z0 * 805459861u,  hz1 = (uint32_t)z1 * 805459861u;
            i000 = (hx0 ^ hy0 ^ hz0) & HASH_MASK;
            i001 = (hx0 ^ hy0 ^ hz1) & HASH_MASK;
            i010 = (hx0 ^ hy1 ^ hz0) & HASH_MASK;
            i011 = (hx0 ^ hy1 ^ hz1) & HASH_MASK;
            i100 = (hx1 ^ hy0 ^ hz0) & HASH_MASK;
            i101 = (hx1 ^ hy0 ^ hz1) & HASH_MASK;
            i110 = (hx1 ^ hy1 ^ hz0) & HASH_MASK;
            i111 = (hx1 ^ hy1 ^ hz1) & HASH_MASK;
        }

        const float2* tb = (const float2*)tables + (size_t)l * HASH_SIZE;
        float2 t000 = __ldg(tb + i000);
        float2 t001 = __ldg(tb + i001);
        float2 t010 = __ldg(tb + i010);
        float2 t011 = __ldg(tb + i011);
        float2 t100 = __ldg(tb + i100);
        float2 t101 = __ldg(tb + i101);
        float2 t110 = __ldg(tb + i110);
        float2 t111 = __ldg(tb + i111);

        float ux = 1.0f - wx, uy = 1.0f - wy, uz = 1.0f - wz;
        float w000 = ux*uy*uz, w001 = ux*uy*wz, w010 = ux*wy*uz, w011 = ux*wy*wz;
        float w100 = wx*uy*uz, w101 = wx*uy*wz, w110 = wx*wy*uz, w111 = wx*wy*wz;

        float f0 = w000*t000.x + w001*t001.x + w010*t010.x + w011*t011.x
                 + w100*t100.x + w101*t101.x + w110*t110.x + w111*t111.x;
        float f1 = w000*t000.y + w001*t001.y + w010*t010.y + w011*t011.y
                 + w100*t100.y + w101*t101.y + w110*t110.y + w111*t111.y;

        const float* colp = sW0T + (39 + 2*l) * 64;
        addin(acc, f0, colp);
        addin(acc, f1, colp + 64);
    }

    // ---- activation after layer0 ----
#pragma unroll
    for (int j = 0; j < 64; j++) acc[j] = sp100(acc[j]);

    // ---- layer1: output-major (h1 in regs, h2 staged to smem) ----
#pragma unroll 1
    for (int o = 0; o < 64; o++) {
        const float4* wr = (const float4*)(sW1 + o * 64);
        float s = sb1[o];
#pragma unroll
        for (int q = 0; q < 16; q++) {
            float4 w = wr[q];
            s += w.x * acc[4*q+0] + w.y * acc[4*q+1] + w.z * acc[4*q+2] + w.w * acc[4*q+3];
        }
        h2s[o * NTHREADS + tid] = sp100(s);
    }

    // ---- layer2: input-major streaming over h2 ----
    float o17[17];
#pragma unroll
    for (int o = 0; o < 17; o++) o17[o] = sb2[o];
#pragma unroll 1
    for (int j = 0; j < 64; j++) {
        float v = h2s[j * NTHREADS + tid];
        const float* wc = sW2T + j * 20;
#pragma unroll
        for (int o = 0; o < 17; o++) o17[o] += v * wc[o];
    }
    float* op = out + (size_t)n * 17;
#pragma unroll
    for (int o = 0; o < 17; o++) op[o] = o17[o];
}

extern "C" void kernel_launch(void* const* d_in, const int* in_sizes, int n_in,
                              void* d_out, int out_size)
{
    const float* x  = (const float*)d_in[0];
    const float* tb = (const float*)d_in[1];
    const float* W0 = (const float*)d_in[2];
    const float* b0 = (const float*)d_in[3];
    const float* W1 = (const float*)d_in[4];
    const float* b1 = (const float*)d_in[5];
    const float* W2 = (const float*)d_in[6];
    const float* b2 = (const float*)d_in[7];
    float* out = (float*)d_out;

    int npts = in_sizes[0] / 3;

    // RESOLUTIONS computed with the same libm double ops the reference's numpy uses
    // (same container/libm) so ceil boundaries (esp. level 15 at ~2048.0) match exactly.
    LParams lp;
    double scale = exp2(log2(2048.0 / 16.0) / 15.0);
    for (int l = 0; l < 16; l++) {
        int R = (int)ceil(16.0 * pow(scale, (double)l));
        lp.R[l]     = R;
        lp.rm1[l]   = (float)(R - 1);
        lp.dense[l] = ((long long)R * R * R <= (long long)HASH_SIZE) ? 1 : 0;
    }

    int smem_bytes = (71*64 + 64*64 + 64*20 + 64 + 64 + 32 + 64*NTHREADS) * (int)sizeof(float);
    cudaFuncSetAttribute(nerf_fused, cudaFuncAttributeMaxDynamicSharedMemorySize, smem_bytes);

    int blocks = (npts + NTHREADS - 1) / NTHREADS;
    nerf_fused<<<blocks, NTHREADS, smem_bytes>>>(x, tb, W0, b0, W1, b1, W2, b2, out, npts, lp);
}

// round 2
// speedup vs baseline: 1.0911x; 1.0911x over previous
#include <cuda_runtime.h>
#include <math.h>
#include <stdint.h>

#define HASH_SIZE  (1u << 19)
#define HASH_MASK  (HASH_SIZE - 1u)
#define NT 128

typedef unsigned long long ull;

struct LParams {
    float rm1[16];
    int   R[16];
    int   dense[16];
};

__device__ __forceinline__ void fma2(ull &acc, ull a, ull b) {
    asm("fma.rn.f32x2 %0, %1, %2, %0;" : "+l"(acc) : "l"(a), "l"(b));
}
__device__ __forceinline__ ull pack2(float x, float y) {
    ull r; asm("mov.b64 %0, {%1, %2};" : "=l"(r) : "f"(x), "f"(y)); return r;
}
__device__ __forceinline__ float2 unpack2(ull v) {
    float2 r; asm("mov.b64 {%0, %1}, %2;" : "=f"(r.x), "=f"(r.y) : "l"(v)); return r;
}

__device__ __forceinline__ float sp100(float v) {
    float z = v * 100.0f;
    if (z > 20.0f) return v;
    return 0.01f * log1pf(expf(z));
}

// Each lane owns 32 hidden units (half = tid&1) for BOTH points of its lane pair.
// accS: accumulators for this lane's own point; accO: for the partner's point.
__device__ __forceinline__ void addin2(ull accS[16], ull accO[16],
                                       float vS, float vO, const float* col32) {
    const ulonglong2* c = (const ulonglong2*)col32;   // 8 x 16B = 32 floats
    ull a = pack2(vS, vS);
    ull b = pack2(vO, vO);
#pragma unroll
    for (int q = 0; q < 8; q++) {
        ulonglong2 w = c[q];
        fma2(accS[2*q+0], a, w.x);
        fma2(accS[2*q+1], a, w.y);
        fma2(accO[2*q+0], b, w.x);
        fma2(accO[2*q+1], b, w.y);
    }
}

__global__ void __launch_bounds__(NT, 4) nerf_fused(
    const float* __restrict__ xin,
    const float* __restrict__ tables,
    const float* __restrict__ W0, const float* __restrict__ b0,
    const float* __restrict__ W1, const float* __restrict__ b1,
    const float* __restrict__ W2, const float* __restrict__ b2,
    float* __restrict__ out, int npts, LParams lp)
{
    __shared__ __align__(16) float sW0T[71*64];  // col i contiguous: sW0T[i*64+j] = W0[j][i]
    __shared__ __align__(16) float sW1 [64*64];  // row-major
    __shared__ __align__(16) float sW2T[64*20];  // sW2T[j*20+o] = W2[o][j], pad o=17..19 with 0
    __shared__ __align__(16) float sb0[64];
    __shared__ __align__(16) float sb1[64];
    __shared__ __align__(16) float sb2p[20];

    const int tid = threadIdx.x;
    for (int k = tid; k < 71*64; k += NT) { int i = k >> 6, j = k & 63; sW0T[k] = W0[j*71 + i]; }
    for (int k = tid; k < 64*64; k += NT) sW1[k] = W1[k];
    for (int k = tid; k < 64*20; k += NT) { int j = k / 20, o = k % 20; sW2T[k] = (o < 17) ? W2[o*64 + j] : 0.0f; }
    if (tid < 64) { sb0[tid] = b0[tid]; sb1[tid] = b1[tid]; }
    if (tid < 20) sb2p[tid] = (tid < 17) ? b2[tid] : 0.0f;
    __syncthreads();

    const int gid = blockIdx.x * NT + tid;
    const int n   = (gid < npts) ? gid : (npts - 1);
    const int half = tid & 1;
    const int hb   = half * 32;
    const float* colHalf = sW0T + hb;

    const float px = xin[n*3+0], py = xin[n*3+1], pz = xin[n*3+2];

    ull accS[16], accO[16];
#pragma unroll
    for (int q = 0; q < 16; q++) {
        ull bv = pack2(sb0[hb + 2*q], sb0[hb + 2*q + 1]);
        accS[q] = bv;
        accO[q] = bv;
    }

    // ---- inputs 0..2: raw x ----
    {
        float vO;
        vO = __shfl_xor_sync(0xffffffffu, px, 1); addin2(accS, accO, px, vO, colHalf + 0*64);
        vO = __shfl_xor_sync(0xffffffffu, py, 1); addin2(accS, accO, py, vO, colHalf + 1*64);
        vO = __shfl_xor_sync(0xffffffffu, pz, 1); addin2(accS, accO, pz, vO, colHalf + 2*64);
    }

    // ---- inputs 3..38: positional embedding ----
#pragma unroll 1
    for (int m = 0; m < 6; m++) {
        float f = (float)(1 << m);
        float sx, cx, sy, cy, sz, cz;
        sincosf(px * f, &sx, &cx);
        sincosf(py * f, &sy, &cy);
        sincosf(pz * f, &sz, &cz);
        const float* base = colHalf + (3 + 6*m) * 64;
        float vO;
        vO = __shfl_xor_sync(0xffffffffu, sx, 1); addin2(accS, accO, sx, vO, base + 0*64);
        vO = __shfl_xor_sync(0xffffffffu, sy, 1); addin2(accS, accO, sy, vO, base + 1*64);
        vO = __shfl_xor_sync(0xffffffffu, sz, 1); addin2(accS, accO, sz, vO, base + 2*64);
        vO = __shfl_xor_sync(0xffffffffu, cx, 1); addin2(accS, accO, cx, vO, base + 3*64);
        vO = __shfl_xor_sync(0xffffffffu, cy, 1); addin2(accS, accO, cy, vO, base + 4*64);
        vO = __shfl_xor_sync(0xffffffffu, cz, 1); addin2(accS, accO, cz, vO, base + 5*64);
    }

    // ---- inputs 39..70: hash-grid features ----
#pragma unroll 1
    for (int l = 0; l < 16; l++) {
        const float rm1 = lp.rm1[l];
        const int   R   = lp.R[l];
        float fx = px * rm1, fy = py * rm1, fz = pz * rm1;
        float p0x = floorf(fx), p0y = floorf(fy), p0z = floorf(fz);
        float wx = fx - p0x, wy = fy - p0y, wz = fz - p0z;
        int ix = (int)p0x, iy = (int)p0y, iz = (int)p0z;
        int x0 = max(min(ix,     R-1), 0), x1 = max(min(ix + 1, R-1), 0);
        int y0 = max(min(iy,     R-1), 0), y1 = max(min(iy + 1, R-1), 0);
        int z0 = max(min(iz,     R-1), 0), z1 = max(min(iz + 1, R-1), 0);

        uint32_t i000, i001, i010, i011, i100, i101, i110, i111;
        if (lp.dense[l]) {
            int R2 = R * R;
            int az0 = z0 * R2, az1 = z1 * R2;
            int ay0 = y0 * R,  ay1 = y1 * R;
            i000 = (uint32_t)(x0 + ay0 + az0);
            i001 = (uint32_t)(x0 + ay0 + az1);
            i010 = (uint32_t)(x0 + ay1 + az0);
            i011 = (uint32_t)(x0 + ay1 + az1);
            i100 = (uint32_t)(x1 + ay0 + az0);
            i101 = (uint32_t)(x1 + ay0 + az1);
            i110 = (uint32_t)(x1 + ay1 + az0);
            i111 = (uint32_t)(x1 + ay1 + az1);
        } else {
            uint32_t hx0 = (uint32_t)x0,               hx1 = (uint32_t)x1;
            uint32_t hy0 = (uint32_t)y0 * 2654435761u, hy1 = (uint32_t)y1 * 2654435761u;
            uint32_t hz0 = (uint32_t)z0 * 805459861u,  hz1 = (uint32_t)z1 * 805459861u;
            i000 = (hx0 ^ hy0 ^ hz0) & HASH_MASK;
            i001 = (hx0 ^ hy0 ^ hz1) & HASH_MASK;
            i010 = (hx0 ^ hy1 ^ hz0) & HASH_MASK;
            i011 = (hx0 ^ hy1 ^ hz1) & HASH_MASK;
            i100 = (hx1 ^ hy0 ^ hz0) & HASH_MASK;
            i101 = (hx1 ^ hy0 ^ hz1) & HASH_MASK;
            i110 = (hx1 ^ hy1 ^ hz0) & HASH_MASK;
            i111 = (hx1 ^ hy1 ^ hz1) & HASH_MASK;
        }

        const float2* tb = (const float2*)tables + (size_t)l * HASH_SIZE;
        float2 t000 = __ldg(tb + i000);
        float2 t001 = __ldg(tb + i001);
        float2 t010 = __ldg(tb + i010);
        float2 t011 = __ldg(tb + i011);
        float2 t100 = __ldg(tb + i100);
        float2 t101 = __ldg(tb + i101);
        float2 t110 = __ldg(tb + i110);
        float2 t111 = __ldg(tb + i111);

        float ux = 1.0f - wx, uy = 1.0f - wy, uz = 1.0f - wz;
        float w000 = ux*uy*uz, w001 = ux*uy*wz, w010 = ux*wy*uz, w011 = ux*wy*wz;
        float w100 = wx*uy*uz, w101 = wx*uy*wz, w110 = wx*wy*uz, w111 = wx*wy*wz;

        float f0 = w000*t000.x + w001*t001.x + w010*t010.x + w011*t011.x
                 + w100*t100.x + w101*t101.x + w110*t110.x + w111*t111.x;
        float f1 = w000*t000.y + w001*t001.y + w010*t010.y + w011*t011.y
                 + w100*t100.y + w101*t101.y + w110*t110.y + w111*t111.y;

        const float* colp = colHalf + (39 + 2*l) * 64;
        float f0O = __shfl_xor_sync(0xffffffffu, f0, 1);
        float f1O = __shfl_xor_sync(0xffffffffu, f1, 1);
        addin2(accS, accO, f0, f0O, colp);
        addin2(accS, accO, f1, f1O, colp + 64);
    }

    // ---- activation after layer0 ----
#pragma unroll
    for (int q = 0; q < 16; q++) {
        float2 a = unpack2(accS[q]);
        accS[q] = pack2(sp100(a.x), sp100(a.y));
        float2 b = unpack2(accO[q]);
        accO[q] = pack2(sp100(b.x), sp100(b.y));
    }

    // ---- layers 1+2 fused: stream h2 rows into 17 output accumulators ----
    // Lane holds h1[hb..hb+32] for self (accS) and partner (accO) points.
    // For each row r: partial over own j-half for both points; the partner's
    // "other-point" partial is this lane's point's missing half -> one shfl.
    ull o17[9];
#pragma unroll
    for (int t = 0; t < 9; t++) o17[t] = pack2(sb2p[2*t], sb2p[2*t+1]);

#pragma unroll 2
    for (int r = 0; r < 64; r++) {
        const ulonglong2* wr = (const ulonglong2*)(sW1 + r*64 + hb);
        ull sS = 0, sO = 0;
#pragma unroll
        for (int q = 0; q < 8; q++) {
            ulonglong2 w = wr[q];
            fma2(sS, w.x, accS[2*q+0]);
            fma2(sS, w.y, accS[2*q+1]);
            fma2(sO, w.x, accO[2*q+0]);
            fma2(sO, w.y, accO[2*q+1]);
        }
        float2 fs = unpack2(sS);
        float2 fo = unpack2(sO);
        float pS = fs.x + fs.y;
        float pO = fo.x + fo.y;
        float cross = __shfl_xor_sync(0xffffffffu, pO, 1);
        float h = pS + cross + sb1[r];
        float v = sp100(h);
        ull vv = pack2(v, v);
        const ull* w2 = (const ull*)(sW2T + r*20);
#pragma unroll
        for (int t = 0; t < 9; t++) fma2(o17[t], vv, w2[t]);
    }

    if (gid < npts) {
        float* op = out + (size_t)gid * 17;
#pragma unroll
        for (int t = 0; t < 8; t++) {
            float2 v = unpack2(o17[t]);
            op[2*t+0] = v.x;
            op[2*t+1] = v.y;
        }
        op[16] = unpack2(o17[8]).x;
    }
}

extern "C" void kernel_launch(void* const* d_in, const int* in_sizes, int n_in,
                              void* d_out, int out_size)
{
    const float* x  = (const float*)d_in[0];
    const float* tb = (const float*)d_in[1];
    const float* W0 = (const float*)d_in[2];
    const float* b0 = (const float*)d_in[3];
    const float* W1 = (const float*)d_in[4];
    const float* b1 = (const float*)d_in[5];
    const float* W2 = (const float*)d_in[6];
    const float* b2 = (const float*)d_in[7];
    float* out = (float*)d_out;

    int npts = in_sizes[0] / 3;

    LParams lp;
    double scale = exp2(log2(2048.0 / 16.0) / 15.0);
    for (int l = 0; l < 16; l++) {
        int R = (int)ceil(16.0 * pow(scale, (double)l));
        lp.R[l]     = R;
        lp.rm1[l]   = (float)(R - 1);
        lp.dense[l] = ((long long)R * R * R <= (long long)HASH_SIZE) ? 1 : 0;
    }

    int blocks = (npts + NT - 1) / NT;
    nerf_fused<<<blocks, NT>>>(x, tb, W0, b0, W1, b1, W2, b2, out, npts, lp);
}

// round 3
// speedup vs baseline: 1.5940x; 1.4609x over previous
#include <cuda_runtime.h>
#include <math.h>
#include <stdint.h>

#define HASH_SIZE  (1u << 19)
#define HASH_MASK  (HASH_SIZE - 1u)
#define NT 128
#define NBINS (1 << 18)     // 64^3 Morton bins
#define MAXPTS (1 << 20)

typedef unsigned long long ull;

struct LParams {
    float rm1[16];
    int   R[16];
    int   dense[16];
};

// ---- static scratch (no allocations allowed) ----
__device__ int g_bins[NBINS];
__device__ int g_cnt[NBINS];
__device__ int g_binStart[NBINS];
__device__ int g_partials[256];
__device__ int g_keys[MAXPTS];
__device__ int g_perm[MAXPTS];

__device__ __forceinline__ void fma2(ull &acc, ull a, ull b) {
    asm("fma.rn.f32x2 %0, %1, %2, %0;" : "+l"(acc) : "l"(a), "l"(b));
}
__device__ __forceinline__ ull pack2(float x, float y) {
    ull r; asm("mov.b64 %0, {%1, %2};" : "=l"(r) : "f"(x), "f"(y)); return r;
}
__device__ __forceinline__ float2 unpack2(ull v) {
    float2 r; asm("mov.b64 {%0, %1}, %2;" : "=f"(r.x), "=f"(r.y) : "l"(v)); return r;
}
__device__ __forceinline__ float sp100(float v) {
    float z = v * 100.0f;
    if (z > 20.0f) return v;
    return 0.01f * log1pf(expf(z));
}

// ---------------- sort pipeline ----------------
__device__ __forceinline__ uint32_t part3(uint32_t x) {
    x &= 0x3Fu;
    x = (x | (x << 16)) & 0x030000FFu;
    x = (x | (x << 8))  & 0x0300F00Fu;
    x = (x | (x << 4))  & 0x030C30C3u;
    x = (x | (x << 2))  & 0x09249249u;
    return x;
}

__global__ void k_zero() {
    int i = blockIdx.x * blockDim.x + threadIdx.x;
    if (i < NBINS) { g_bins[i] = 0; g_cnt[i] = 0; }
}

__global__ void k_hist(const float* __restrict__ x, int npts) {
    int i = blockIdx.x * blockDim.x + threadIdx.x;
    if (i >= npts) return;
    float px = x[3*i], py = x[3*i+1], pz = x[3*i+2];
    int kx = min(max((int)(px * 64.0f), 0), 63);
    int ky = min(max((int)(py * 64.0f), 0), 63);
    int kz = min(max((int)(pz * 64.0f), 0), 63);
    uint32_t key = part3(kx) | (part3(ky) << 1) | (part3(kz) << 2);
    g_keys[i] = (int)key;
    atomicAdd(&g_bins[key], 1);
}

__global__ void k_scan1() {            // 256 blocks x 1024
    __shared__ int s[1024];
    int t = threadIdx.x;
    int g = blockIdx.x * 1024 + t;
    int v = g_bins[g];
    s[t] = v; __syncthreads();
#pragma unroll
    for (int d = 1; d < 1024; d <<= 1) {
        int add = (t >= d) ? s[t-d] : 0;
        __syncthreads();
        s[t] += add;
        __syncthreads();
    }
    g_binStart[g] = s[t] - v;
    if (t == 1023) g_partials[blockIdx.x] = s[t];
}

__global__ void k_scan2() {            // 1 block x 256
    __shared__ int s[256];
    int t = threadIdx.x;
    int v = g_partials[t];
    s[t] = v; __syncthreads();
#pragma unroll
    for (int d = 1; d < 256; d <<= 1) {
        int add = (t >= d) ? s[t-d] : 0;
        __syncthreads();
        s[t] += add;
        __syncthreads();
    }
    g_partials[t] = s[t] - v;
}

__global__ void k_scan3() {            // 256 blocks x 1024
    int g = blockIdx.x * 1024 + threadIdx.x;
    g_binStart[g] += g_partials[blockIdx.x];
}

__global__ void k_scatter(int npts) {
    int i = blockIdx.x * blockDim.x + threadIdx.x;
    if (i >= npts) return;
    int k = g_keys[i];
    int pos = g_binStart[k] + atomicAdd(&g_cnt[k], 1);
    g_perm[pos] = i;
}

// ---------------- fused main kernel ----------------
// Weight layouts (conflict-free for even/odd half split):
//   sW0T: stride 72 per input column; even half at +0 (32 floats), odd at +36.
//   sW1p: stride 72 per row; even half [0..31] at +0, odd [32..63] at +36.
//   sW2T: stride 20 per hidden j: W2[o][j] at [j*20+o], o=17..19 zero.
__device__ __forceinline__ void addin2(ull accS[16], ull accO[16],
                                       float vS, float vO, const float* col32) {
    const ulonglong2* c = (const ulonglong2*)col32;
    ull a = pack2(vS, vS);
    ull b = pack2(vO, vO);
#pragma unroll
    for (int q = 0; q < 8; q++) {
        ulonglong2 w = c[q];
        fma2(accS[2*q+0], a, w.x);
        fma2(accS[2*q+1], a, w.y);
        fma2(accO[2*q+0], b, w.x);
        fma2(accO[2*q+1], b, w.y);
    }
}

__global__ void __launch_bounds__(NT, 4) nerf_fused(
    const float* __restrict__ xin,
    const float* __restrict__ tables,
    const float* __restrict__ W0, const float* __restrict__ b0,
    const float* __restrict__ W1, const float* __restrict__ b1,
    const float* __restrict__ W2, const float* __restrict__ b2,
    float* __restrict__ out, int npts, LParams lp)
{
    __shared__ __align__(16) float sW0T[71*72];   // also reused as output stage
    __shared__ __align__(16) float sW1p[64*72];
    __shared__ __align__(16) float sW2T[64*20];
    __shared__ float sb0[64];
    __shared__ float sb1[64];
    __shared__ float sb2p[20];
    __shared__ int   sRow[NT];

    const int tid = threadIdx.x;
    for (int k = tid; k < 71*64; k += NT) {
        int i = k >> 6, j = k & 63;
        int jo = (j < 32) ? j : (j + 4);           // odd half at +36
        sW0T[i*72 + jo] = W0[j*71 + i];
    }
    for (int k = tid; k < 64*64; k += NT) {
        int r = k >> 6, j = k & 63;
        int jo = (j < 32) ? j : (j + 4);
        sW1p[r*72 + jo] = W1[k];
    }
    for (int k = tid; k < 64*20; k += NT) {
        int j = k / 20, o = k % 20;
        sW2T[k] = (o < 17) ? W2[o*64 + j] : 0.0f;
    }
    if (tid < 64) { sb0[tid] = b0[tid]; sb1[tid] = b1[tid]; }
    if (tid < 20) sb2p[tid] = (tid < 17) ? b2[tid] : 0.0f;
    __syncthreads();

    const int gid = blockIdx.x * NT + tid;
    const bool valid = (gid < npts);
    const int n = valid ? g_perm[gid] : g_perm[0];
    const int half = tid & 1;
    const float* colHalf = sW0T + half * 36;

    const float px = xin[n*3+0], py = xin[n*3+1], pz = xin[n*3+2];

    ull accS[16], accO[16];
    const int hb = half * 32;
#pragma unroll
    for (int q = 0; q < 16; q++) {
        ull bv = pack2(sb0[hb + 2*q], sb0[hb + 2*q + 1]);
        accS[q] = bv;
        accO[q] = bv;
    }

    // inputs 0..2
    {
        float vO;
        vO = __shfl_xor_sync(0xffffffffu, px, 1); addin2(accS, accO, px, vO, colHalf + 0*72);
        vO = __shfl_xor_sync(0xffffffffu, py, 1); addin2(accS, accO, py, vO, colHalf + 1*72);
        vO = __shfl_xor_sync(0xffffffffu, pz, 1); addin2(accS, accO, pz, vO, colHalf + 2*72);
    }

    // inputs 3..38: positional embedding
#pragma unroll 1
    for (int m = 0; m < 6; m++) {
        float f = (float)(1 << m);
        float sx, cx, sy, cy, sz, cz;
        sincosf(px * f, &sx, &cx);
        sincosf(py * f, &sy, &cy);
        sincosf(pz * f, &sz, &cz);
        const float* base = colHalf + (3 + 6*m) * 72;
        float vO;
        vO = __shfl_xor_sync(0xffffffffu, sx, 1); addin2(accS, accO, sx, vO, base + 0*72);
        vO = __shfl_xor_sync(0xffffffffu, sy, 1); addin2(accS, accO, sy, vO, base + 1*72);
        vO = __shfl_xor_sync(0xffffffffu, sz, 1); addin2(accS, accO, sz, vO, base + 2*72);
        vO = __shfl_xor_sync(0xffffffffu, cx, 1); addin2(accS, accO, cx, vO, base + 3*72);
        vO = __shfl_xor_sync(0xffffffffu, cy, 1); addin2(accS, accO, cy, vO, base + 4*72);
        vO = __shfl_xor_sync(0xffffffffu, cz, 1); addin2(accS, accO, cz, vO, base + 5*72);
    }

    // inputs 39..70: hash-grid features
#pragma unroll 1
    for (int l = 0; l < 16; l++) {
        const float rm1 = lp.rm1[l];
        const int   R   = lp.R[l];
        float fx = px * rm1, fy = py * rm1, fz = pz * rm1;
        float p0x = floorf(fx), p0y = floorf(fy), p0z = floorf(fz);
        float wx = fx - p0x, wy = fy - p0y, wz = fz - p0z;
        int ix = (int)p0x, iy = (int)p0y, iz = (int)p0z;
        int x0 = max(min(ix,     R-1), 0), x1 = max(min(ix + 1, R-1), 0);
        int y0 = max(min(iy,     R-1), 0), y1 = max(min(iy + 1, R-1), 0);
        int z0 = max(min(iz,     R-1), 0), z1 = max(min(iz + 1, R-1), 0);

        uint32_t i000, i001, i010, i011, i100, i101, i110, i111;
        if (lp.dense[l]) {
            int R2 = R * R;
            int az0 = z0 * R2, az1 = z1 * R2;
            int ay0 = y0 * R,  ay1 = y1 * R;
            i000 = (uint32_t)(x0 + ay0 + az0);
            i001 = (uint32_t)(x0 + ay0 + az1);
            i010 = (uint32_t)(x0 + ay1 + az0);
            i011 = (uint32_t)(x0 + ay1 + az1);
            i100 = (uint32_t)(x1 + ay0 + az0);
            i101 = (uint32_t)(x1 + ay0 + az1);
            i110 = (uint32_t)(x1 + ay1 + az0);
            i111 = (uint32_t)(x1 + ay1 + az1);
        } else {
            uint32_t hx0 = (uint32_t)x0,               hx1 = (uint32_t)x1;
            uint32_t hy0 = (uint32_t)y0 * 2654435761u, hy1 = (uint32_t)y1 * 2654435761u;
            uint32_t hz0 = (uint32_t)z0 * 805459861u,  hz1 = (uint32_t)z1 * 805459861u;
            i000 = (hx0 ^ hy0 ^ hz0) & HASH_MASK;
            i001 = (hx0 ^ hy0 ^ hz1) & HASH_MASK;
            i010 = (hx0 ^ hy1 ^ hz0) & HASH_MASK;
            i011 = (hx0 ^ hy1 ^ hz1) & HASH_MASK;
            i100 = (hx1 ^ hy0 ^ hz0) & HASH_MASK;
            i101 = (hx1 ^ hy0 ^ hz1) & HASH_MASK;
            i110 = (hx1 ^ hy1 ^ hz0) & HASH_MASK;
            i111 = (hx1 ^ hy1 ^ hz1) & HASH_MASK;
        }

        const float2* tb = (const float2*)tables + (size_t)l * HASH_SIZE;
        float2 t000 = __ldg(tb + i000);
        float2 t001 = __ldg(tb + i001);
        float2 t010 = __ldg(tb + i010);
        float2 t011 = __ldg(tb + i011);
        float2 t100 = __ldg(tb + i100);
        float2 t101 = __ldg(tb + i101);
        float2 t110 = __ldg(tb + i110);
        float2 t111 = __ldg(tb + i111);

        float ux = 1.0f - wx, uy = 1.0f - wy, uz = 1.0f - wz;
        float w000 = ux*uy*uz, w001 = ux*uy*wz, w010 = ux*wy*uz, w011 = ux*wy*wz;
        float w100 = wx*uy*uz, w101 = wx*uy*wz, w110 = wx*wy*uz, w111 = wx*wy*wz;

        float f0 = w000*t000.x + w001*t001.x + w010*t010.x + w011*t011.x
                 + w100*t100.x + w101*t101.x + w110*t110.x + w111*t111.x;
        float f1 = w000*t000.y + w001*t001.y + w010*t010.y + w011*t011.y
                 + w100*t100.y + w101*t101.y + w110*t110.y + w111*t111.y;

        const float* colp = colHalf + (39 + 2*l) * 72;
        float f0O = __shfl_xor_sync(0xffffffffu, f0, 1);
        float f1O = __shfl_xor_sync(0xffffffffu, f1, 1);
        addin2(accS, accO, f0, f0O, colp);
        addin2(accS, accO, f1, f1O, colp + 72);
    }

    // activation
#pragma unroll
    for (int q = 0; q < 16; q++) {
        float2 a = unpack2(accS[q]);
        accS[q] = pack2(sp100(a.x), sp100(a.y));
        float2 b = unpack2(accO[q]);
        accO[q] = pack2(sp100(b.x), sp100(b.y));
    }

    // layers 1+2 fused
    ull o17[9];
#pragma unroll
    for (int t = 0; t < 9; t++) o17[t] = pack2(sb2p[2*t], sb2p[2*t+1]);

#pragma unroll 2
    for (int r = 0; r < 64; r++) {
        const ulonglong2* wr = (const ulonglong2*)(sW1p + r*72 + half*36);
        ull sS = 0, sO = 0;
#pragma unroll
        for (int q = 0; q < 8; q++) {
            ulonglong2 w = wr[q];
            fma2(sS, w.x, accS[2*q+0]);
            fma2(sS, w.y, accS[2*q+1]);
            fma2(sO, w.x, accO[2*q+0]);
            fma2(sO, w.y, accO[2*q+1]);
        }
        float2 fs = unpack2(sS);
        float2 fo = unpack2(sO);
        float pS = fs.x + fs.y;
        float pO = fo.x + fo.y;
        float cross = __shfl_xor_sync(0xffffffffu, pO, 1);
        float v = sp100(pS + cross + sb1[r]);
        ull vv = pack2(v, v);
        const ulonglong2* w2q = (const ulonglong2*)(sW2T + r*20);
#pragma unroll
        for (int q = 0; q < 4; q++) {
            ulonglong2 w = w2q[q];
            fma2(o17[2*q+0], vv, w.x);
            fma2(o17[2*q+1], vv, w.y);
        }
        fma2(o17[8], vv, *(const ull*)(sW2T + r*20 + 16));
    }

    // ---- stage outputs to smem (reuse sW0T), then warp-cooperative scattered row writes ----
    __syncthreads();                   // everyone done reading sW0T
    float* stage = sW0T;               // 128*17 = 2176 floats < 71*72
    sRow[tid] = valid ? n : -1;
#pragma unroll
    for (int t = 0; t < 8; t++) {
        float2 v = unpack2(o17[t]);
        stage[tid*17 + 2*t + 0] = v.x;
        stage[tid*17 + 2*t + 1] = v.y;
    }
    stage[tid*17 + 16] = unpack2(o17[8]).x;
    __syncthreads();

    const int wid = tid >> 5, lane = tid & 31;
    if (lane < 17) {
#pragma unroll 1
        for (int r = wid*32; r < wid*32 + 32; r++) {
            int rowIdx = sRow[r];
            if (rowIdx >= 0) out[(size_t)rowIdx*17 + lane] = stage[r*17 + lane];
        }
    }
}

extern "C" void kernel_launch(void* const* d_in, const int* in_sizes, int n_in,
                              void* d_out, int out_size)
{
    const float* x  = (const float*)d_in[0];
    const float* tb = (const float*)d_in[1];
    const float* W0 = (const float*)d_in[2];
    const float* b0 = (const float*)d_in[3];
    const float* W1 = (const float*)d_in[4];
    const float* b1 = (const float*)d_in[5];
    const float* W2 = (const float*)d_in[6];
    const float* b2 = (const float*)d_in[7];
    float* out = (float*)d_out;

    int npts = in_sizes[0] / 3;

    LParams lp;
    double scale = exp2(log2(2048.0 / 16.0) / 15.0);
    for (int l = 0; l < 16; l++) {
        int R = (int)ceil(16.0 * pow(scale, (double)l));
        lp.R[l]     = R;
        lp.rm1[l]   = (float)(R - 1);
        lp.dense[l] = ((long long)R * R * R <= (long long)HASH_SIZE) ? 1 : 0;
    }

    // ---- sort pipeline ----
    k_zero<<<(NBINS + 255)/256, 256>>>();
    k_hist<<<(npts + 255)/256, 256>>>(x, npts);
    k_scan1<<<NBINS/1024, 1024>>>();
    k_scan2<<<1, 256>>>();
    k_scan3<<<NBINS/1024, 1024>>>();
    k_scatter<<<(npts + 255)/256, 256>>>(npts);

    // ---- fused main ----
    int blocks = (npts + NT - 1) / NT;
    nerf_fused<<<blocks, NT>>>(x, tb, W0, b0, W1, b1, W2, b2, out, npts, lp);
}